// round 3
// baseline (speedup 1.0000x reference)
#include <cuda_runtime.h>
#include <cstdint>

#define B      2
#define NNODE  50000
#define IN_DIM 64
#define HID    256
#define OUT    128
#define NEDGE  500000

#define NPB 16   // nodes per block (node mlp)
#define EPB 16   // edges per block (edge mlp)
#define DPB 16   // nodes per block (decode)

// Scratch (allocation-guard-safe __device__ globals)
__device__ float g_H[(size_t)B * NNODE * OUT];   // 51.2 MB accumulator
__device__ int   g_eu[NEDGE];
__device__ int   g_ev[NEDGE];
__device__ int   g_is64;

// ---------------------------------------------------------------------------
// Kernel 0a: detect whether edges buffer is int64 or int32.
// int64 data: all high words (odd 32-bit words) are 0 since values < 50000.
// int32 data: odd words are v-indices, ~uniform in [0,50000) -> nonzero w.h.p.
// ---------------------------------------------------------------------------
__global__ void detect_edge_dtype_kernel(const int* __restrict__ e32)
{
    if (threadIdx.x == 0 && blockIdx.x == 0) {
        int all_zero = 1;
        #pragma unroll 1
        for (int i = 1; i < 256; i += 2)
            if (e32[i] != 0) { all_zero = 0; break; }
        g_is64 = all_zero;
    }
}

// Kernel 0b: normalize edges into SoA int32 arrays
__global__ __launch_bounds__(256) void convert_edges_kernel(const int* __restrict__ e32)
{
    const int e = blockIdx.x * 256 + threadIdx.x;
    if (e < NEDGE) {
        if (g_is64) {            // words: [u_lo, u_hi, v_lo, v_hi]
            g_eu[e] = e32[4 * e + 0];
            g_ev[e] = e32[4 * e + 2];
        } else {                 // words: [u, v]
            g_eu[e] = e32[2 * e + 0];
            g_ev[e] = e32[2 * e + 1];
        }
    }
}

// ---------------------------------------------------------------------------
// Kernel 1: H[b,n,:] = relu(x[b,n,:] @ nw1 + nb1) @ nw2 + nb2
// ---------------------------------------------------------------------------
__global__ __launch_bounds__(256) void node_mlp_kernel(
    const float* __restrict__ x,
    const float* __restrict__ nw1, const float* __restrict__ nb1,
    const float* __restrict__ nw2, const float* __restrict__ nb2)
{
    __shared__ __align__(16) float xs[NPB][IN_DIM];   // 4 KB
    __shared__ __align__(16) float hs[NPB][HID];      // 16 KB

    const int base = blockIdx.x * NPB;   // flattened node index in [0, B*N)
    const int t = threadIdx.x;

    for (int i = t; i < NPB * IN_DIM; i += 256)
        xs[i / IN_DIM][i % IN_DIM] = x[(size_t)(base + i / IN_DIM) * IN_DIM + (i % IN_DIM)];
    __syncthreads();

    // hidden: thread t owns hidden unit j=t for all NPB nodes
    float acc[NPB];
    {
        const float b1 = nb1[t];
        #pragma unroll
        for (int n = 0; n < NPB; n++) acc[n] = b1;
    }
    #pragma unroll 4
    for (int k = 0; k < IN_DIM; k += 4) {
        const float w0 = nw1[(k + 0) * HID + t];
        const float w1 = nw1[(k + 1) * HID + t];
        const float w2 = nw1[(k + 2) * HID + t];
        const float w3 = nw1[(k + 3) * HID + t];
        #pragma unroll
        for (int n = 0; n < NPB; n++) {
            float4 v = *reinterpret_cast<const float4*>(&xs[n][k]);
            acc[n] = fmaf(v.x, w0, acc[n]);
            acc[n] = fmaf(v.y, w1, acc[n]);
            acc[n] = fmaf(v.z, w2, acc[n]);
            acc[n] = fmaf(v.w, w3, acc[n]);
        }
    }
    #pragma unroll
    for (int n = 0; n < NPB; n++) hs[n][t] = fmaxf(acc[n], 0.0f);
    __syncthreads();

    const int o   = t & (OUT - 1);
    const int nb0 = (t >> 7) * (NPB / 2);
    float oacc[NPB / 2];
    {
        const float b2 = nb2[o];
        #pragma unroll
        for (int n = 0; n < NPB / 2; n++) oacc[n] = b2;
    }
    #pragma unroll 4
    for (int k = 0; k < HID; k += 4) {
        const float w0 = nw2[(k + 0) * OUT + o];
        const float w1 = nw2[(k + 1) * OUT + o];
        const float w2 = nw2[(k + 2) * OUT + o];
        const float w3 = nw2[(k + 3) * OUT + o];
        #pragma unroll
        for (int n = 0; n < NPB / 2; n++) {
            float4 v = *reinterpret_cast<const float4*>(&hs[nb0 + n][k]);
            oacc[n] = fmaf(v.x, w0, oacc[n]);
            oacc[n] = fmaf(v.y, w1, oacc[n]);
            oacc[n] = fmaf(v.z, w2, oacc[n]);
            oacc[n] = fmaf(v.w, w3, oacc[n]);
        }
    }
    #pragma unroll
    for (int n = 0; n < NPB / 2; n++)
        g_H[(size_t)(base + nb0 + n) * OUT + o] = oacc[n];
}

// ---------------------------------------------------------------------------
// Kernel 2: per edge e in batch b:
//   emb = relu(concat(x[b,u],x[b,v]) @ ew1 + eb1) @ ew2 + eb2
//   H[b,u,:] += emb; H[b,v,:] += emb   (atomics)
// ---------------------------------------------------------------------------
__global__ __launch_bounds__(256) void edge_mlp_kernel(
    const float* __restrict__ x,
    const float* __restrict__ ew1, const float* __restrict__ eb1,
    const float* __restrict__ ew2, const float* __restrict__ eb2)
{
    __shared__ __align__(16) float es[EPB][2 * IN_DIM];  // 8 KB
    __shared__ __align__(16) float hs[EPB][HID];         // 16 KB
    __shared__ int us[EPB], vs[EPB];

    const long long idx = (long long)blockIdx.x * EPB;   // in [0, B*E); NEDGE % EPB == 0
    const int b  = (int)(idx / NEDGE);
    const int e0 = (int)(idx % NEDGE);
    const int t = threadIdx.x;

    if (t < EPB) {
        us[t] = g_eu[e0 + t];
        vs[t] = g_ev[e0 + t];
    }
    __syncthreads();

    // gather concat(x[u], x[v]) tile (x is 25.6 MB -> L2-resident)
    const float* xb = x + (size_t)b * NNODE * IN_DIM;
    for (int i = t; i < EPB * 2 * IN_DIM; i += 256) {
        const int ei = i / (2 * IN_DIM);
        const int c  = i % (2 * IN_DIM);
        const int node = (c < IN_DIM) ? us[ei] : vs[ei];
        es[ei][c] = xb[(size_t)node * IN_DIM + (c & (IN_DIM - 1))];
    }
    __syncthreads();

    // hidden
    float acc[EPB];
    {
        const float b1 = eb1[t];
        #pragma unroll
        for (int n = 0; n < EPB; n++) acc[n] = b1;
    }
    #pragma unroll 4
    for (int k = 0; k < 2 * IN_DIM; k += 4) {
        const float w0 = ew1[(k + 0) * HID + t];
        const float w1 = ew1[(k + 1) * HID + t];
        const float w2 = ew1[(k + 2) * HID + t];
        const float w3 = ew1[(k + 3) * HID + t];
        #pragma unroll
        for (int n = 0; n < EPB; n++) {
            float4 v = *reinterpret_cast<const float4*>(&es[n][k]);
            acc[n] = fmaf(v.x, w0, acc[n]);
            acc[n] = fmaf(v.y, w1, acc[n]);
            acc[n] = fmaf(v.z, w2, acc[n]);
            acc[n] = fmaf(v.w, w3, acc[n]);
        }
    }
    #pragma unroll
    for (int n = 0; n < EPB; n++) hs[n][t] = fmaxf(acc[n], 0.0f);
    __syncthreads();

    // out + scatter
    const int o   = t & (OUT - 1);
    const int eb0 = (t >> 7) * (EPB / 2);
    float oacc[EPB / 2];
    {
        const float b2 = eb2[o];
        #pragma unroll
        for (int n = 0; n < EPB / 2; n++) oacc[n] = b2;
    }
    #pragma unroll 4
    for (int k = 0; k < HID; k += 4) {
        const float w0 = ew2[(k + 0) * OUT + o];
        const float w1 = ew2[(k + 1) * OUT + o];
        const float w2 = ew2[(k + 2) * OUT + o];
        const float w3 = ew2[(k + 3) * OUT + o];
        #pragma unroll
        for (int n = 0; n < EPB / 2; n++) {
            float4 v = *reinterpret_cast<const float4*>(&hs[eb0 + n][k]);
            oacc[n] = fmaf(v.x, w0, oacc[n]);
            oacc[n] = fmaf(v.y, w1, oacc[n]);
            oacc[n] = fmaf(v.z, w2, oacc[n]);
            oacc[n] = fmaf(v.w, w3, oacc[n]);
        }
    }
    float* Hb = g_H + (size_t)b * NNODE * OUT;
    #pragma unroll
    for (int n = 0; n < EPB / 2; n++) {
        const int e = eb0 + n;
        atomicAdd(&Hb[(size_t)us[e] * OUT + o], oacc[n]);
        atomicAdd(&Hb[(size_t)vs[e] * OUT + o], oacc[n]);
    }
}

// ---------------------------------------------------------------------------
// Kernel 3: out[b,n,:] = H[b,n,:] @ dw + db    (dw is [OUT, IN_DIM])
// ---------------------------------------------------------------------------
__global__ __launch_bounds__(256) void decode_kernel(
    const float* __restrict__ dw, const float* __restrict__ db,
    float* __restrict__ out)
{
    __shared__ __align__(16) float hs[DPB][OUT];  // 8 KB

    const int base = blockIdx.x * DPB;
    const int t = threadIdx.x;

    for (int i = t; i < DPB * OUT; i += 256)
        hs[i / OUT][i % OUT] = g_H[(size_t)base * OUT + i];
    __syncthreads();

    const int o   = t & (IN_DIM - 1);
    const int nb0 = (t >> 6) * (DPB / 4);
    float acc[DPB / 4];
    {
        const float bb = db[o];
        #pragma unroll
        for (int n = 0; n < DPB / 4; n++) acc[n] = bb;
    }
    #pragma unroll 4
    for (int k = 0; k < OUT; k += 4) {
        const float w0 = dw[(k + 0) * IN_DIM + o];
        const float w1 = dw[(k + 1) * IN_DIM + o];
        const float w2 = dw[(k + 2) * IN_DIM + o];
        const float w3 = dw[(k + 3) * IN_DIM + o];
        #pragma unroll
        for (int n = 0; n < DPB / 4; n++) {
            float4 v = *reinterpret_cast<const float4*>(&hs[nb0 + n][k]);
            acc[n] = fmaf(v.x, w0, acc[n]);
            acc[n] = fmaf(v.y, w1, acc[n]);
            acc[n] = fmaf(v.z, w2, acc[n]);
            acc[n] = fmaf(v.w, w3, acc[n]);
        }
    }
    #pragma unroll
    for (int n = 0; n < DPB / 4; n++)
        out[(size_t)(base + nb0 + n) * IN_DIM + o] = acc[n];
}

// ---------------------------------------------------------------------------
// Inputs (metadata order):
//  0: x [B,N,64] f32   1: edges [E,2] (int32 OR int64 -- detected at runtime)
//  2: ew1 [128,256]    3: eb1 [256]   4: ew2 [256,128]   5: eb2 [128]
//  6: nw1 [64,256]     7: nb1 [256]   8: nw2 [256,128]   9: nb2 [128]
// 10: dw [128,64]     11: db [64]     out: [B,N,64] f32
// ---------------------------------------------------------------------------
extern "C" void kernel_launch(void* const* d_in, const int* in_sizes, int n_in,
                              void* d_out, int out_size)
{
    const float* x     = (const float*)d_in[0];
    const int*   e32   = (const int*)d_in[1];
    const float* ew1   = (const float*)d_in[2];
    const float* eb1   = (const float*)d_in[3];
    const float* ew2   = (const float*)d_in[4];
    const float* eb2   = (const float*)d_in[5];
    const float* nw1   = (const float*)d_in[6];
    const float* nb1   = (const float*)d_in[7];
    const float* nw2   = (const float*)d_in[8];
    const float* nb2   = (const float*)d_in[9];
    const float* dw    = (const float*)d_in[10];
    const float* db    = (const float*)d_in[11];
    float*       out   = (float*)d_out;

    const int total_nodes = B * NNODE;                    // 100000
    const long long total_edges = (long long)B * NEDGE;   // 1000000

    detect_edge_dtype_kernel<<<1, 32>>>(e32);
    convert_edges_kernel<<<(NEDGE + 255) / 256, 256>>>(e32);
    node_mlp_kernel<<<total_nodes / NPB, 256>>>(x, nw1, nb1, nw2, nb2);
    edge_mlp_kernel<<<(unsigned)(total_edges / EPB), 256>>>(x, ew1, eb1, ew2, eb2);
    decode_kernel<<<total_nodes / DPB, 256>>>(dw, db, out);
}